// round 13
// baseline (speedup 1.0000x reference)
#include <cuda_runtime.h>
#include <cuda_bf16.h>
#include <cstdint>

// Decoder (Conv-TasNet): out = overlap_add( (mixture_w * est_mask)^T @ W^T, step=L/2 )
// mixture_w/est_mask [B, N, K] f32, W [L, N] f32, out [B, T] f32
// B=4, N=512, K=16000, L=16, step=8, T = 8*(K-1)+16 = 128008
//
// R13 = R9/R10 datapath (KPT=4, 8xLDG.128 batches = the only config measured
// at 2.1 GB/s/warp) with residency fixed: __launch_bounds__(64,12) caps regs
// at 85 so 12 blocks (24 warps) fit per SM, and the wave-2 tail shrinks to
// 13% (R10 died on an 88-reg/11-block cap + 24% tail, not on the datapath).

#define DEC_B 4
#define DEC_N 512
#define DEC_K 16000
#define DEC_L 16
#define DEC_STEP 8
#define DEC_T (DEC_STEP * (DEC_K - 1) + DEC_L)   // 128008

#define TPB 64
#define NSPLIT 8
#define NCHUNK (DEC_N / NSPLIT)      // 64
#define KPT 4                         // frames per thread (float4 along k)
#define NB 4                          // n's per batch -> 8 LDG.128 in flight
#define NACC 20                       // f32x2 accumulators (40 out positions)

typedef unsigned long long u64t;

#define FMA_F32X2(d, a, b, c) \
    asm("fma.rn.f32x2 %0, %1, %2, %3;" : "=l"(d) : "l"(a), "l"(b), "l"(c))

__global__ __launch_bounds__(TPB, 12)
void decoder_kernel(const float* __restrict__ mw,
                    const float* __restrict__ em,
                    const float* __restrict__ W,
                    float* __restrict__ out)
{
    // This block's N-chunk of W, transposed: Ws[n_local][l]. 4 KB.
    __shared__ __align__(16) float Ws[NCHUNK * DEC_L];
    const int nb = blockIdx.z * NCHUNK;
    for (int i = threadIdx.x; i < NCHUNK * DEC_L; i += TPB) {
        int n = i >> 4;
        int l = i & 15;
        Ws[i] = W[l * DEC_N + nb + n];
    }
    __syncthreads();

    const int b  = blockIdx.y;
    const int k0 = (blockIdx.x * TPB + threadIdx.x) * KPT;
    if (k0 >= DEC_K) return;   // tail guard (63*64*4 = 16128 > 16000; K%4==0)

    // 32-bit float4 indexing: total input float4s = 8.19M < 2^31.
    const float4* __restrict__ mw4 = reinterpret_cast<const float4*>(mw);
    const float4* __restrict__ em4 = reinterpret_cast<const float4*>(em);
    unsigned idx = ((unsigned)b * (DEC_N * DEC_K) + (unsigned)nb * DEC_K + (unsigned)k0) >> 2;
    const unsigned kstr = DEC_K / 4;   // float4 stride between n rows

    // 40 fp32 out positions as 20 f32x2 pairs. Frame f (0..3) covers
    // positions 8f..8f+15 = pairs 4f..4f+7.
    u64t accp[NACC];
#pragma unroll
    for (int i = 0; i < NACC; ++i) accp[i] = 0ull;

    // One n-step: 4 FMUL + 4 packs + 4 LDS.128 (quarter-wise, 4 live W regs)
    // + 32 FFMA2, serving 4 frames.
    auto step = [&](int n, float4 m, float4 e) {
        float p0 = m.x * e.x;
        float p1 = m.y * e.y;
        float p2 = m.z * e.z;
        float p3 = m.w * e.w;
        u64t pp[KPT];
        asm("mov.b64 %0, {%1, %1};" : "=l"(pp[0]) : "f"(p0));
        asm("mov.b64 %0, {%1, %1};" : "=l"(pp[1]) : "f"(p1));
        asm("mov.b64 %0, {%1, %1};" : "=l"(pp[2]) : "f"(p2));
        asm("mov.b64 %0, {%1, %1};" : "=l"(pp[3]) : "f"(p3));

        const ulonglong2* wq = reinterpret_cast<const ulonglong2*>(&Ws[n * DEC_L]);
#pragma unroll
        for (int q = 0; q < 4; ++q) {
            ulonglong2 w2 = wq[q];      // pairs j = 2q, 2q+1
#pragma unroll
            for (int f = 0; f < KPT; ++f) {
                FMA_F32X2(accp[4 * f + 2 * q],     w2.x, pp[f], accp[4 * f + 2 * q]);
                FMA_F32X2(accp[4 * f + 2 * q + 1], w2.y, pp[f], accp[4 * f + 2 * q + 1]);
            }
        }
    };

#pragma unroll 1
    for (int n0 = 0; n0 < NCHUNK; n0 += NB) {
        // Batch: 8 independent coalesced streaming LDG.128s (32 lines in flight).
        float4 m[NB], e[NB];
#pragma unroll
        for (int j = 0; j < NB; ++j) {
            m[j] = __ldcs(&mw4[idx + (unsigned)j * kstr]);
            e[j] = __ldcs(&em4[idx + (unsigned)j * kstr]);
        }
        idx += (unsigned)NB * kstr;
#pragma unroll
        for (int j = 0; j < NB; ++j) step(n0 + j, m[j], e[j]);
    }

    // Scatter-add 40 unique positions (frames k0..k0+3). Interior overlaps
    // merged in registers; <= 2*NSPLIT = 16 atomic fp32 contributions per
    // output element (order-insensitive).
    float* __restrict__ op = out + (unsigned)b * DEC_T + (unsigned)k0 * DEC_STEP;
#pragma unroll
    for (int i = 0; i < NACC; ++i) {
        float lo, hi;
        asm("mov.b64 {%0, %1}, %2;" : "=f"(lo), "=f"(hi) : "l"(accp[i]));
        atomicAdd(&op[2 * i],     lo);
        atomicAdd(&op[2 * i + 1], hi);
    }
}

extern "C" void kernel_launch(void* const* d_in, const int* in_sizes, int n_in,
                              void* d_out, int out_size)
{
    const float* mixture_w = (const float*)d_in[0];  // [B, N, K]
    const float* est_mask  = (const float*)d_in[1];  // [B, N, K]
    const float* W         = (const float*)d_in[2];  // [L, N]
    float* out = (float*)d_out;                       // [B, T]

    cudaMemsetAsync(out, 0, (size_t)out_size * sizeof(float), 0);

    dim3 grid((DEC_K + TPB * KPT - 1) / (TPB * KPT), DEC_B, NSPLIT);  // (63, 4, 8)
    decoder_kernel<<<grid, TPB>>>(mixture_w, est_mask, W, out);
}

// round 14
// speedup vs baseline: 1.3522x; 1.3522x over previous
#include <cuda_runtime.h>
#include <cuda_bf16.h>
#include <cstdint>

// Decoder (Conv-TasNet): out = overlap_add( (mixture_w * est_mask)^T @ W^T, step=L/2 )
// mixture_w/est_mask [B, N, K] f32, W [L, N] f32, out [B, T] f32
// B=4, N=512, K=16000, L=16, step=8, T = 8*(K-1)+16 = 128008
//
// R14 = R7 datapath (the 61.5us best: KPT=2, NSPLIT=4, FFMA2, ulonglong2 W
// reads, NB=4 batches) at TPB=64 so the grid quadruples along K:
// grid (125,4,4) = 2000 blocks = 13.5/SM, single wave, ~27 warps/SM resident
// (R7 was grid-starved at 6.8 blocks/SM, below its own 8-block register cap).
// 125*64*2 = 16000 exactly -> no tail threads.

#define DEC_B 4
#define DEC_N 512
#define DEC_K 16000
#define DEC_L 16
#define DEC_STEP 8
#define DEC_T (DEC_STEP * (DEC_K - 1) + DEC_L)   // 128008

#define TPB 64
#define NSPLIT 4
#define NCHUNK (DEC_N / NSPLIT)      // 128
#define KPT 2                         // frames per thread (float2 along k)
#define NB 4                          // n's per load batch (8 LDG.64 in flight)
#define NACC 12                       // f32x2 accumulators (24 out positions)

typedef unsigned long long u64t;

#define FMA_F32X2(d, a, b, c) \
    asm("fma.rn.f32x2 %0, %1, %2, %3;" : "=l"(d) : "l"(a), "l"(b), "l"(c))

__global__ __launch_bounds__(TPB)
void decoder_kernel(const float* __restrict__ mw,
                    const float* __restrict__ em,
                    const float* __restrict__ W,
                    float* __restrict__ out)
{
    // This block's N-chunk of W, transposed: Ws[n_local][l]. 8 KB.
    __shared__ __align__(16) float Ws[NCHUNK * DEC_L];
    const int nb = blockIdx.z * NCHUNK;
    for (int i = threadIdx.x; i < NCHUNK * DEC_L; i += TPB) {
        int n = i >> 4;
        int l = i & 15;
        Ws[i] = W[l * DEC_N + nb + n];
    }
    __syncthreads();

    const int b  = blockIdx.y;
    const int k0 = (blockIdx.x * TPB + threadIdx.x) * KPT;   // always < 16000

    const size_t base = (size_t)b * DEC_N * DEC_K + (size_t)nb * DEC_K + k0;
    const float2* __restrict__ mwp = reinterpret_cast<const float2*>(mw + base);
    const float2* __restrict__ emp = reinterpret_cast<const float2*>(em + base);
    const size_t kstr = DEC_K / 2;   // float2 stride between n rows

    // 24 fp32 accumulators as 12 x f32x2. Frame k0 -> accp[0..7],
    // frame k0+1 -> accp[4..11] (overlap of 8 positions = 4 pairs).
    u64t accp[NACC];
#pragma unroll
    for (int i = 0; i < NACC; ++i) accp[i] = 0ull;

    // One n-step: 2 FMUL + 2 packs + 4 LDS.128 + 16 FFMA2.
    auto step = [&](int n, float2 m, float2 e) {
        float p0 = m.x * e.x;
        float p1 = m.y * e.y;
        u64t pp0, pp1;
        asm("mov.b64 %0, {%1, %1};" : "=l"(pp0) : "f"(p0));
        asm("mov.b64 %0, {%1, %1};" : "=l"(pp1) : "f"(p1));

        const ulonglong2* w = reinterpret_cast<const ulonglong2*>(&Ws[n * DEC_L]);
        ulonglong2 w0 = w[0];
        ulonglong2 w1 = w[1];
        ulonglong2 w2 = w[2];
        ulonglong2 w3 = w[3];

        FMA_F32X2(accp[0],  w0.x, pp0, accp[0]);
        FMA_F32X2(accp[1],  w0.y, pp0, accp[1]);
        FMA_F32X2(accp[2],  w1.x, pp0, accp[2]);
        FMA_F32X2(accp[3],  w1.y, pp0, accp[3]);
        FMA_F32X2(accp[4],  w2.x, pp0, accp[4]);
        FMA_F32X2(accp[5],  w2.y, pp0, accp[5]);
        FMA_F32X2(accp[6],  w3.x, pp0, accp[6]);
        FMA_F32X2(accp[7],  w3.y, pp0, accp[7]);
        FMA_F32X2(accp[4],  w0.x, pp1, accp[4]);
        FMA_F32X2(accp[5],  w0.y, pp1, accp[5]);
        FMA_F32X2(accp[6],  w1.x, pp1, accp[6]);
        FMA_F32X2(accp[7],  w1.y, pp1, accp[7]);
        FMA_F32X2(accp[8],  w2.x, pp1, accp[8]);
        FMA_F32X2(accp[9],  w2.y, pp1, accp[9]);
        FMA_F32X2(accp[10], w3.x, pp1, accp[10]);
        FMA_F32X2(accp[11], w3.y, pp1, accp[11]);
    };

#pragma unroll 1
    for (int n0 = 0; n0 < NCHUNK; n0 += NB) {
        // Batch: 8 independent coalesced streaming LDG.64s.
        float2 m[NB], e[NB];
#pragma unroll
        for (int j = 0; j < NB; ++j) {
            m[j] = __ldcs(&mwp[(size_t)(n0 + j) * kstr]);
            e[j] = __ldcs(&emp[(size_t)(n0 + j) * kstr]);
        }
#pragma unroll
        for (int j = 0; j < NB; ++j) step(n0 + j, m[j], e[j]);
    }

    // Scatter-add 24 unique positions (frames k0, k0+1). <= 2*NSPLIT = 8 fp32
    // contributions per output element (atomic, order-insensitive).
    float* __restrict__ op = out + (size_t)b * DEC_T + (size_t)k0 * DEC_STEP;
#pragma unroll
    for (int i = 0; i < NACC; ++i) {
        float lo, hi;
        asm("mov.b64 {%0, %1}, %2;" : "=f"(lo), "=f"(hi) : "l"(accp[i]));
        atomicAdd(&op[2 * i],     lo);
        atomicAdd(&op[2 * i + 1], hi);
    }
}

extern "C" void kernel_launch(void* const* d_in, const int* in_sizes, int n_in,
                              void* d_out, int out_size)
{
    const float* mixture_w = (const float*)d_in[0];  // [B, N, K]
    const float* est_mask  = (const float*)d_in[1];  // [B, N, K]
    const float* W         = (const float*)d_in[2];  // [L, N]
    float* out = (float*)d_out;                       // [B, T]

    cudaMemsetAsync(out, 0, (size_t)out_size * sizeof(float), 0);

    dim3 grid(DEC_K / (TPB * KPT), DEC_B, NSPLIT);   // (125, 4, 4) = 2000 blocks
    decoder_kernel<<<grid, TPB>>>(mixture_w, est_mask, W, out);
}